// round 15
// baseline (speedup 1.0000x reference)
#include <cuda_runtime.h>
#include <cuda_fp16.h>
#include <cstdint>

#define B_SZ   8
#define L_SEQ  4096
#define NDIM   256
#define HDIM   256
#define BL     (B_SZ * L_SEQ)        // 32768
#define CHUNK  128
#define NCHUNK (L_SEQ / CHUNK)       // 32
#define SEGS   4
#define SEGLEN (CHUNK / SEGS)        // 32

// ---------------- scratch (device globals; no cudaMalloc allowed) ----------
__device__ __align__(256) __half2 g_Buh[(size_t)BL * NDIM];      // 33.5 MB (fp16 complex)
__device__ __align__(256) __half  g_xh[(size_t)BL * HDIM];       // 16 MB
__device__ __align__(256) __half  g_W2[2 * NDIM * HDIM];         // [512][256] fp16
__device__ __align__(256) __half  g_C2[HDIM * 2 * NDIM];         // [256][512] fp16
__device__ float2 g_Lam[NDIM];
__device__ float2 g_Lam32[NDIM];                    // Lambda^SEGLEN
__device__ float2 g_LamPowC[NCHUNK * NDIM];         // (Lambda^CHUNK)^k
__device__ float2 g_segE[(size_t)B_SZ * NCHUNK * SEGS * NDIM];  // 2 MB segment ends
__device__ float2 g_carryE[B_SZ * NCHUNK * NDIM];   // chunk-local end states

// ---------------- helpers ----------------------------------------------------
__device__ __forceinline__ void cp16(unsigned dst, const void* src) {
    asm volatile("cp.async.cg.shared.global [%0], [%1], 16;" :: "r"(dst), "l"(src));
}

__device__ __forceinline__ void ldm_x4(unsigned* r, unsigned addr) {
    asm volatile("ldmatrix.sync.aligned.m8n8.x4.shared.b16 {%0,%1,%2,%3}, [%4];"
                 : "=r"(r[0]), "=r"(r[1]), "=r"(r[2]), "=r"(r[3]) : "r"(addr));
}

__device__ __forceinline__ void mma_f16(float* c, const unsigned* a, const unsigned* b) {
    asm volatile("mma.sync.aligned.m16n8k16.row.col.f32.f16.f16.f32 "
                 "{%0,%1,%2,%3}, {%4,%5,%6,%7}, {%8,%9}, {%0,%1,%2,%3};"
                 : "+f"(c[0]), "+f"(c[1]), "+f"(c[2]), "+f"(c[3])
                 : "r"(a[0]), "r"(a[1]), "r"(a[2]), "r"(a[3]), "r"(b[0]), "r"(b[1]));
}

#define CP_COMMIT() asm volatile("cp.async.commit_group;" ::: "memory")
#define CP_WAIT1()  asm volatile("cp.async.wait_group 1;" ::: "memory")

// ---------------- fused prep: W rows, C rows, Lambda tables -----------------
__global__ void prep_all_kernel(const float* __restrict__ nu_log,
                                const float* __restrict__ theta_log,
                                const float* __restrict__ B_re,
                                const float* __restrict__ B_im,
                                const float* __restrict__ C_re,
                                const float* __restrict__ C_im) {
    const int bid = blockIdx.x;
    if (bid < NDIM) {
        int n = bid, h = threadIdx.x;
        float r = expf(-expf(nu_log[n]));
        float gamma = sqrtf(fmaxf(1.0f - r * r, 0.0f));
        g_W2[(2 * n) * HDIM + h]     = __float2half_rn(B_re[n * HDIM + h] * gamma);
        g_W2[(2 * n + 1) * HDIM + h] = __float2half_rn(B_im[n * HDIM + h] * gamma);
    } else if (bid < NDIM + HDIM) {
        int h = bid - NDIM, k = threadIdx.x;
        *(__half2*)(g_C2 + h * 512 + 2 * k) =
            __halves2half2(__float2half_rn(C_re[h * NDIM + k]),
                           __float2half_rn(-C_im[h * NDIM + k]));
    } else {
        int n = threadIdx.x;
        float nu  = expf(nu_log[n]);
        float th  = expf(theta_log[n]);
        float r   = expf(-nu);
        float lre = r * cosf(th);
        float lim = r * sinf(th);
        g_Lam[n] = make_float2(lre, lim);
        // Lambda^32 via 5 double squarings
        double pr = lre, pi = lim;
        #pragma unroll
        for (int s = 0; s < 5; ++s) {
            double nr = pr * pr - pi * pi;
            double ni = 2.0 * pr * pi;
            pr = nr; pi = ni;
        }
        g_Lam32[n] = make_float2((float)pr, (float)pi);
        // Lambda^128 = (Lambda^32)^4 via 2 more squarings
        #pragma unroll
        for (int s = 0; s < 2; ++s) {
            double nr = pr * pr - pi * pi;
            double ni = 2.0 * pr * pi;
            pr = nr; pi = ni;
        }
        double qr = 1.0, qi = 0.0;
        #pragma unroll 1
        for (int k = 0; k < NCHUNK; ++k) {
            g_LamPowC[k * NDIM + n] = make_float2((float)qr, (float)qi);
            double nr = qr * pr - qi * pi;
            double ni = qr * pi + qi * pr;
            qr = nr; qi = ni;
        }
    }
}

__global__ __launch_bounds__(256) void prep_x_kernel(const float* __restrict__ x) {
    size_t i = ((size_t)blockIdx.x * 256 + threadIdx.x) * 4;
    float4 v = *(const float4*)(x + i);
    *(__half2*)(g_xh + i)     = __halves2half2(__float2half_rn(v.x), __float2half_rn(v.y));
    *(__half2*)(g_xh + i + 2) = __halves2half2(__float2half_rn(v.z), __float2half_rn(v.w));
}

// ---------------- gemm1: fp16 mma.sync GEMM (unchanged, proven) --------------
#define GSTAGES 3
#define GBK     64
#define A_STG_BYTES (128 * 128)
#define B_STG_BYTES (128 * 128)
#define SLOT_BYTES  (A_STG_BYTES + B_STG_BYTES)   // 32768
#define G_SMEM_BYTES (GSTAGES * SLOT_BYTES)       // 98304

__global__ __launch_bounds__(256, 2) void gemm1_kernel() {
    extern __shared__ __align__(1024) char smem[];
    const unsigned sbase = (unsigned)__cvta_generic_to_shared(smem);
    const __half* A = g_xh;
    const __half* B = g_W2;
    constexpr int K = HDIM, NOUT = 2 * NDIM;

    const int t = threadIdx.x, lane = t & 31, warp = t >> 5;
    const int wm = warp >> 1, wn = warp & 1;
    const int bm = blockIdx.y * 128, bn = blockIdx.x * 128;
    constexpr int NCH = K / GBK;

    float acc[2][8][4];
    #pragma unroll
    for (int i = 0; i < 2; ++i)
        #pragma unroll
        for (int j = 0; j < 8; ++j)
            #pragma unroll
            for (int q = 0; q < 4; ++q) acc[i][j][q] = 0.f;

    auto load_chunk = [&](int c) {
        const int slot = c % GSTAGES;
        const int kk0  = c * GBK;
        const unsigned abase = sbase + slot * SLOT_BYTES;
        const unsigned bbase = abase + A_STG_BYTES;
        #pragma unroll
        for (int i = 0; i < 4; ++i) {
            int idx = t + i * 256;
            int r = idx >> 3, g = idx & 7;
            cp16(abase + (unsigned)(r * 128 + ((g ^ (r & 7)) << 4)),
                 A + (size_t)(bm + r) * K + kk0 + g * 8);
        }
        #pragma unroll
        for (int i = 0; i < 4; ++i) {
            int idx = t + i * 256;
            int r = idx >> 3, g = idx & 7;
            cp16(bbase + (unsigned)(r * 128 + ((g ^ (r & 7)) << 4)),
                 B + (size_t)(bn + r) * K + kk0 + g * 8);
        }
    };

    load_chunk(0); CP_COMMIT();
    load_chunk(1); CP_COMMIT();

    const int ar0 = wm * 32 + (lane & 15);
    const int ar1 = ar0 + 16;
    const int akc = lane >> 4;
    const int brb = wn * 64 + (lane & 7) + ((lane >> 4) << 3);
    const int bkc = (lane >> 3) & 1;

    #pragma unroll 1
    for (int c = 0; c < NCH; ++c) {
        CP_WAIT1();
        __syncthreads();
        if (c + 2 < NCH) load_chunk(c + 2);
        CP_COMMIT();

        const int slot = c % GSTAGES;
        const unsigned abase = sbase + slot * SLOT_BYTES;
        const unsigned bbase = abase + A_STG_BYTES;

        #pragma unroll
        for (int kk = 0; kk < GBK; kk += 16) {
            unsigned a[2][4], b[4][4];
            {
                int kc = (kk >> 3) + akc;
                ldm_x4(a[0], abase + (unsigned)(ar0 * 128 + ((kc ^ (ar0 & 7)) << 4)));
                ldm_x4(a[1], abase + (unsigned)(ar1 * 128 + ((kc ^ (ar1 & 7)) << 4)));
            }
            #pragma unroll
            for (int p = 0; p < 4; ++p) {
                int br = brb + p * 16;
                int kc = (kk >> 3) + bkc;
                ldm_x4(b[p], bbase + (unsigned)(br * 128 + ((kc ^ (br & 7)) << 4)));
            }
            #pragma unroll
            for (int mt = 0; mt < 2; ++mt)
                #pragma unroll
                for (int nt = 0; nt < 8; ++nt)
                    mma_f16(acc[mt][nt], a[mt], &b[nt >> 1][(nt & 1) * 2]);
        }
    }

    // epilogue: Bu as fp16 complex pairs
    #pragma unroll
    for (int mt = 0; mt < 2; ++mt)
        #pragma unroll
        for (int nt = 0; nt < 8; ++nt) {
            const int row = bm + wm * 32 + mt * 16 + (lane >> 2);
            const int col = bn + wn * 64 + nt * 8 + (lane & 3) * 2;
            const float* c = acc[mt][nt];
            g_Buh[(size_t)row * NDIM + (col >> 1)] =
                __halves2half2(__float2half_rn(c[0]), __float2half_rn(c[1]));
            g_Buh[(size_t)(row + 8) * NDIM + (col >> 1)] =
                __halves2half2(__float2half_rn(c[2]), __float2half_rn(c[3]));
        }
}

// ---------------- scanA: segment ends + chunk-end carries (R13) -------------
__global__ __launch_bounds__(1024) void scanA_kernel() {
    __shared__ float2 e[SEGS * NDIM];
    const int tid = threadIdx.x;
    const int col = tid & 255, seg = tid >> 8;
    const int bc = blockIdx.x;
    const float2 lam = g_Lam[col];
    float2 s = make_float2(0.f, 0.f);
    const __half2* p = g_Buh + (size_t)bc * CHUNK * NDIM
                             + (size_t)seg * SEGLEN * NDIM + col;

    #pragma unroll 1
    for (int j0 = 0; j0 < SEGLEN; j0 += 8) {
        float2 b[8];
        #pragma unroll
        for (int u = 0; u < 8; ++u)
            b[u] = __half22float2(p[(size_t)(j0 + u) * NDIM]);
        #pragma unroll
        for (int u = 0; u < 8; ++u) {
            float sx = fmaf(lam.x, s.x, fmaf(-lam.y, s.y, b[u].x));
            float sy = fmaf(lam.x, s.y, fmaf( lam.y, s.x, b[u].y));
            s = make_float2(sx, sy);
        }
    }
    e[tid] = s;
    g_segE[(size_t)bc * SEGS * NDIM + tid] = s;
    __syncthreads();

    if (tid < NDIM) {
        const float2 l32 = g_Lam32[tid];
        float2 acc = e[tid];
        #pragma unroll
        for (int sg = 1; sg < SEGS; ++sg) {
            float2 es = e[sg * NDIM + tid];
            float ax = fmaf(l32.x, acc.x, fmaf(-l32.y, acc.y, es.x));
            float ay = fmaf(l32.x, acc.y, fmaf( l32.y, acc.x, es.y));
            acc = make_float2(ax, ay);
        }
        g_carryE[(size_t)bc * NDIM + tid] = acc;
    }
}

// ---------------- fused scanC + gemm2 ----------------------------------------
// One block per chunk (bm = bc*128). Phase 1: rescan with carry, S tile -> smem
// (128 x 512 fp16, 8 BK-chunks of [128][128B], ldmatrix swizzle). Phase 2:
// K=512 GEMM vs C2 with A smem-resident; B 3-stage cp.async ring; 2 N-halves.
// smem: A 131072 | B 3x16384 | cs 8192  = 188416 bytes.
#define F_A_OFF   0u
#define F_B_OFF   131072u
#define F_CS_OFF  180224u
#define F_SMEM_BYTES 188416

__global__ __launch_bounds__(1024, 1) void scan_gemm2_kernel(
    const float* __restrict__ D, float* __restrict__ y)
{
    extern __shared__ __align__(1024) char smem[];
    const unsigned sbase = (unsigned)__cvta_generic_to_shared(smem);
    float2* cs = (float2*)(smem + F_CS_OFF);

    const int tid = threadIdx.x;
    const int bc = blockIdx.x;
    const int b = bc >> 5, c = bc & 31;          // NCHUNK = 32
    const int bm = bc * 128;

    // ---- B chunk loader: i in [0,16): nhalf = i>>3, kc = i&7 ----
    auto load_bchunk = [&](int i) {
        const int slot = i % 3;
        const int bn = (i >> 3) * 128;
        const int kk0 = (i & 7) * 64;
        const unsigned bb = sbase + F_B_OFF + (unsigned)slot * 16384u;
        int r = tid >> 3, g = tid & 7;           // 1024 threads = 128 rows x 8 granules
        cp16(bb + (unsigned)(r * 128 + ((g ^ (r & 7)) << 4)),
             g_C2 + (size_t)(bn + r) * 512 + kk0 + g * 8);
    };
    load_bchunk(0); CP_COMMIT();
    load_bchunk(1); CP_COMMIT();

    // ---- phase 1: carry prologue + rescan into smem A ----
    const int col = tid & 255, seg = tid >> 8;
    {
        if (tid < NDIM) {
            float2 cin = make_float2(0.f, 0.f);
            #pragma unroll 4
            for (int cp = 0; cp < c; ++cp) {
                float2 P = g_LamPowC[(c - 1 - cp) * NDIM + tid];
                float2 E = g_carryE[((size_t)b * NCHUNK + cp) * NDIM + tid];
                cin.x = fmaf(P.x, E.x, fmaf(-P.y, E.y, cin.x));
                cin.y = fmaf(P.x, E.y, fmaf( P.y, E.x, cin.y));
            }
            const float2 l32 = g_Lam32[tid];
            float2 cc = cin;
            cs[tid] = cc;
            #pragma unroll
            for (int sg = 0; sg < SEGS - 1; ++sg) {
                float2 es = g_segE[(size_t)bc * SEGS * NDIM + sg * NDIM + tid];
                float cx = fmaf(l32.x, cc.x, fmaf(-l32.y, cc.y, es.x));
                float cy = fmaf(l32.x, cc.y, fmaf( l32.y, cc.x, es.y));
                cc = make_float2(cx, cy);
                cs[(sg + 1) * NDIM + tid] = cc;
            }
        }
        __syncthreads();

        const float2 lam = g_Lam[col];
        float2 s = cs[seg * NDIM + col];
        const __half2* p = g_Buh + (size_t)bc * CHUNK * NDIM
                                 + (size_t)seg * SEGLEN * NDIM + col;
        // smem A address components: half cols (2col, 2col+1)
        const unsigned kcbuf = (unsigned)(col >> 5) * 16384u;  // k-chunk buffer
        const int gcol = ((col << 1) >> 3) & 7;                // granule in row
        const int sub  = (col << 1) & 7;                       // half within granule
        #pragma unroll 1
        for (int j0 = 0; j0 < SEGLEN; j0 += 8) {
            float2 b8[8];
            #pragma unroll
            for (int u = 0; u < 8; ++u)
                b8[u] = __half22float2(p[(size_t)(j0 + u) * NDIM]);
            #pragma unroll
            for (int u = 0; u < 8; ++u) {
                float sx = fmaf(lam.x, s.x, fmaf(-lam.y, s.y, b8[u].x));
                float sy = fmaf(lam.x, s.y, fmaf( lam.y, s.x, b8[u].y));
                s = make_float2(sx, sy);
                const int row = seg * SEGLEN + j0 + u;
                unsigned off = kcbuf + (unsigned)(row * 128
                             + ((gcol ^ (row & 7)) << 4) + sub * 2);
                *(__half2*)(smem + off) =
                    __halves2half2(__float2half_rn(sx), __float2half_rn(sy));
            }
        }
    }
    __syncthreads();

    // ---- phase 2: GEMM, A resident in smem ----
    const int lane = tid & 31, warp = tid >> 5;
    const int wm = warp >> 2, wn = warp & 3;     // 8 x 4 warps, tile 16M x 32N
    float acc[4][4];
    #pragma unroll
    for (int nt = 0; nt < 4; ++nt)
        #pragma unroll
        for (int q = 0; q < 4; ++q) acc[nt][q] = 0.f;

    const int ar  = wm * 16 + (lane & 15);
    const int akg = lane >> 4;
    const int br0 = wn * 32 + (lane & 7) + ((lane >> 4) << 3);
    const int bkg = (lane >> 3) & 1;

    #pragma unroll 1
    for (int i = 0; i < 16; ++i) {
        CP_WAIT1();
        __syncthreads();
        if (i + 2 < 16) load_bchunk(i + 2);
        CP_COMMIT();

        const unsigned ab = sbase + (unsigned)(i & 7) * 16384u;
        const unsigned bb = sbase + F_B_OFF + (unsigned)(i % 3) * 16384u;

        #pragma unroll
        for (int kk = 0; kk < 64; kk += 16) {
            unsigned a[4], bf[2][4];
            {
                int kg = (kk >> 3) + akg;
                ldm_x4(a, ab + (unsigned)(ar * 128 + ((kg ^ (ar & 7)) << 4)));
            }
            #pragma unroll
            for (int p2 = 0; p2 < 2; ++p2) {
                int br = br0 + p2 * 16;
                int kg = (kk >> 3) + bkg;
                ldm_x4(bf[p2], bb + (unsigned)(br * 128 + ((kg ^ (br & 7)) << 4)));
            }
            #pragma unroll
            for (int nt = 0; nt < 4; ++nt)
                mma_f16(acc[nt], a, &bf[nt >> 1][(nt & 1) * 2]);
        }

        if ((i & 7) == 7) {
            const int nh = i >> 3;
            const int row = bm + wm * 16 + (lane >> 2);
            #pragma unroll
            for (int nt = 0; nt < 4; ++nt) {
                const int col2 = nh * 128 + wn * 32 + nt * 8 + (lane & 3) * 2;
                float2 d  = *(const float2*)(D + col2);
                float2 x0 = __half22float2(*(const __half2*)(g_xh + (size_t)row * HDIM + col2));
                float2 x1 = __half22float2(*(const __half2*)(g_xh + (size_t)(row + 8) * HDIM + col2));
                *(float2*)(y + (size_t)row * HDIM + col2) =
                    make_float2(acc[nt][0] + x0.x * d.x, acc[nt][1] + x0.y * d.y);
                *(float2*)(y + (size_t)(row + 8) * HDIM + col2) =
                    make_float2(acc[nt][2] + x1.x * d.x, acc[nt][3] + x1.y * d.y);
                acc[nt][0] = acc[nt][1] = acc[nt][2] = acc[nt][3] = 0.f;
            }
        }
    }
}

// ---------------- launch -----------------------------------------------------
extern "C" void kernel_launch(void* const* d_in, const int* in_sizes, int n_in,
                              void* d_out, int out_size) {
    const float* x         = (const float*)d_in[0];
    const float* B_re      = (const float*)d_in[1];
    const float* B_im      = (const float*)d_in[2];
    const float* C_re      = (const float*)d_in[3];
    const float* C_im      = (const float*)d_in[4];
    const float* nu_log    = (const float*)d_in[5];
    const float* theta_log = (const float*)d_in[6];
    const float* D         = (const float*)d_in[7];
    float* y = (float*)d_out;

    cudaFuncSetAttribute(gemm1_kernel,
                         cudaFuncAttributeMaxDynamicSharedMemorySize, G_SMEM_BYTES);
    cudaFuncSetAttribute(scan_gemm2_kernel,
                         cudaFuncAttributeMaxDynamicSharedMemorySize, F_SMEM_BYTES);

    prep_all_kernel<<<NDIM + HDIM + 1, 256>>>(nu_log, theta_log,
                                              B_re, B_im, C_re, C_im);
    prep_x_kernel<<<(BL * HDIM) / 1024, 256>>>(x);
    gemm1_kernel<<<dim3((2 * NDIM) / 128, BL / 128), 256, G_SMEM_BYTES>>>();
    scanA_kernel<<<B_SZ * NCHUNK, 1024>>>();
    scan_gemm2_kernel<<<B_SZ * NCHUNK, 1024, F_SMEM_BYTES>>>(D, y);
}

// round 16
// speedup vs baseline: 1.1536x; 1.1536x over previous
#include <cuda_runtime.h>
#include <cuda_fp16.h>
#include <cstdint>

#define B_SZ   8
#define L_SEQ  4096
#define NDIM   256
#define HDIM   256
#define BL     (B_SZ * L_SEQ)        // 32768
#define CHUNK  128
#define NCHUNK (L_SEQ / CHUNK)       // 32
#define SEGS   4
#define SEGLEN (CHUNK / SEGS)        // 32
#define PX_BLOCKS ((BL * HDIM) / 2048)   // 4096 blocks, 8 floats/thread

// ---------------- scratch (device globals; no cudaMalloc allowed) ----------
__device__ __align__(256) __half2 g_Buh[(size_t)BL * NDIM];      // 33.5 MB (fp16 complex)
__device__ __align__(256) __half  g_xh[(size_t)BL * HDIM];       // 16 MB
__device__ __align__(256) __half  g_Sh[(size_t)BL * 2 * NDIM];   // 32 MB
__device__ __align__(256) __half  g_W2[2 * NDIM * HDIM];         // [512][256] fp16
__device__ __align__(256) __half  g_C2[HDIM * 2 * NDIM];         // [256][512] fp16
__device__ float2 g_Lam[NDIM];
__device__ float2 g_Lam32[NDIM];                    // Lambda^SEGLEN
__device__ float2 g_LamPowC[NCHUNK * NDIM];         // (Lambda^CHUNK)^k
__device__ float2 g_segE[(size_t)B_SZ * NCHUNK * SEGS * NDIM];  // 2 MB segment ends
__device__ float2 g_carryE[B_SZ * NCHUNK * NDIM];   // chunk-local end states

// ---------------- helpers ----------------------------------------------------
__device__ __forceinline__ void cp16(unsigned dst, const void* src) {
    asm volatile("cp.async.cg.shared.global [%0], [%1], 16;" :: "r"(dst), "l"(src));
}

__device__ __forceinline__ void ldm_x4(unsigned* r, unsigned addr) {
    asm volatile("ldmatrix.sync.aligned.m8n8.x4.shared.b16 {%0,%1,%2,%3}, [%4];"
                 : "=r"(r[0]), "=r"(r[1]), "=r"(r[2]), "=r"(r[3]) : "r"(addr));
}

__device__ __forceinline__ void mma_f16(float* c, const unsigned* a, const unsigned* b) {
    asm volatile("mma.sync.aligned.m16n8k16.row.col.f32.f16.f16.f32 "
                 "{%0,%1,%2,%3}, {%4,%5,%6,%7}, {%8,%9}, {%0,%1,%2,%3};"
                 : "+f"(c[0]), "+f"(c[1]), "+f"(c[2]), "+f"(c[3])
                 : "r"(a[0]), "r"(a[1]), "r"(a[2]), "r"(a[3]), "r"(b[0]), "r"(b[1]));
}

#define CP_COMMIT() asm volatile("cp.async.commit_group;" ::: "memory")
#define CP_WAIT1()  asm volatile("cp.async.wait_group 1;" ::: "memory")

// ---------------- single fused prep: x split + W/C rows + Lambda tables -----
__global__ __launch_bounds__(256) void prep_kernel(
    const float* __restrict__ x,
    const float* __restrict__ nu_log,
    const float* __restrict__ theta_log,
    const float* __restrict__ B_re,
    const float* __restrict__ B_im,
    const float* __restrict__ C_re,
    const float* __restrict__ C_im) {
    const int bid = blockIdx.x;
    if (bid < PX_BLOCKS) {
        // x -> fp16, 8 floats per thread
        size_t i = ((size_t)bid * 256 + threadIdx.x) * 8;
        float4 v0 = *(const float4*)(x + i);
        float4 v1 = *(const float4*)(x + i + 4);
        *(__half2*)(g_xh + i)     = __halves2half2(__float2half_rn(v0.x), __float2half_rn(v0.y));
        *(__half2*)(g_xh + i + 2) = __halves2half2(__float2half_rn(v0.z), __float2half_rn(v0.w));
        *(__half2*)(g_xh + i + 4) = __halves2half2(__float2half_rn(v1.x), __float2half_rn(v1.y));
        *(__half2*)(g_xh + i + 6) = __halves2half2(__float2half_rn(v1.z), __float2half_rn(v1.w));
    } else if (bid < PX_BLOCKS + NDIM) {
        int n = bid - PX_BLOCKS, h = threadIdx.x;
        float r = expf(-expf(nu_log[n]));
        float gamma = sqrtf(fmaxf(1.0f - r * r, 0.0f));
        g_W2[(2 * n) * HDIM + h]     = __float2half_rn(B_re[n * HDIM + h] * gamma);
        g_W2[(2 * n + 1) * HDIM + h] = __float2half_rn(B_im[n * HDIM + h] * gamma);
    } else if (bid < PX_BLOCKS + NDIM + HDIM) {
        int h = bid - PX_BLOCKS - NDIM, k = threadIdx.x;
        *(__half2*)(g_C2 + h * 512 + 2 * k) =
            __halves2half2(__float2half_rn(C_re[h * NDIM + k]),
                           __float2half_rn(-C_im[h * NDIM + k]));
    } else {
        int n = threadIdx.x;
        float nu  = expf(nu_log[n]);
        float th  = expf(theta_log[n]);
        float r   = expf(-nu);
        float lre = r * cosf(th);
        float lim = r * sinf(th);
        g_Lam[n] = make_float2(lre, lim);
        // Lambda^32 via 5 double squarings
        double pr = lre, pi = lim;
        #pragma unroll
        for (int s = 0; s < 5; ++s) {
            double nr = pr * pr - pi * pi;
            double ni = 2.0 * pr * pi;
            pr = nr; pi = ni;
        }
        g_Lam32[n] = make_float2((float)pr, (float)pi);
        // Lambda^128 = (Lambda^32)^4 via 2 more squarings
        #pragma unroll
        for (int s = 0; s < 2; ++s) {
            double nr = pr * pr - pi * pi;
            double ni = 2.0 * pr * pi;
            pr = nr; pi = ni;
        }
        double qr = 1.0, qi = 0.0;
        #pragma unroll 1
        for (int k = 0; k < NCHUNK; ++k) {
            g_LamPowC[k * NDIM + n] = make_float2((float)qr, (float)qi);
            double nr = qr * pr - qi * pi;
            double ni = qr * pi + qi * pr;
            qr = nr; qi = ni;
        }
    }
}

// ---------------- fp16 mma.sync GEMM -----------------------------------------
// out[M, NOUT] = A*B^T   (A:[M][K] fp16, B:[NOUT][K] fp16, fp32 accumulate)
// CTA tile 128x128, warp tile 32x64 (8 warps: 4m x 2n), BK=64, 3-stage ring.
#define GSTAGES 3
#define GBK     64
#define A_STG_BYTES (128 * 128)
#define B_STG_BYTES (128 * 128)
#define SLOT_BYTES  (A_STG_BYTES + B_STG_BYTES)   // 32768
#define G_SMEM_BYTES (GSTAGES * SLOT_BYTES)       // 98304

template<int K, int NOUT, bool EPI, bool OUTH>
__device__ __forceinline__ void tc_gemm(
    const __half* __restrict__ A, const __half* __restrict__ B,
    void* __restrict__ outp,
    const __half* __restrict__ xres, const float* __restrict__ Dres)
{
    extern __shared__ __align__(1024) char smem[];
    const unsigned sbase = (unsigned)__cvta_generic_to_shared(smem);

    const int t = threadIdx.x, lane = t & 31, warp = t >> 5;
    const int wm = warp >> 1, wn = warp & 1;          // 4 x 2 warps
    const int bm = blockIdx.y * 128, bn = blockIdx.x * 128;

    constexpr int NCH = K / GBK;

    float acc[2][8][4];
    #pragma unroll
    for (int i = 0; i < 2; ++i)
        #pragma unroll
        for (int j = 0; j < 8; ++j)
            #pragma unroll
            for (int q = 0; q < 4; ++q) acc[i][j][q] = 0.f;

    auto load_chunk = [&](int c) {
        const int slot = c % GSTAGES;
        const int kk0  = c * GBK;
        const unsigned abase = sbase + slot * SLOT_BYTES;
        const unsigned bbase = abase + A_STG_BYTES;
        #pragma unroll
        for (int i = 0; i < 4; ++i) {
            int idx = t + i * 256;
            int r = idx >> 3, g = idx & 7;
            cp16(abase + (unsigned)(r * 128 + ((g ^ (r & 7)) << 4)),
                 A + (size_t)(bm + r) * K + kk0 + g * 8);
        }
        #pragma unroll
        for (int i = 0; i < 4; ++i) {
            int idx = t + i * 256;
            int r = idx >> 3, g = idx & 7;
            cp16(bbase + (unsigned)(r * 128 + ((g ^ (r & 7)) << 4)),
                 B + (size_t)(bn + r) * K + kk0 + g * 8);
        }
    };

    load_chunk(0); CP_COMMIT();
    load_chunk(1); CP_COMMIT();

    const int ar0 = wm * 32 + (lane & 15);
    const int ar1 = ar0 + 16;
    const int akc = lane >> 4;
    const int brb = wn * 64 + (lane & 7) + ((lane >> 4) << 3);
    const int bkc = (lane >> 3) & 1;

    #pragma unroll 1
    for (int c = 0; c < NCH; ++c) {
        CP_WAIT1();
        __syncthreads();

        if (c + 2 < NCH) load_chunk(c + 2);
        CP_COMMIT();

        const int slot = c % GSTAGES;
        const unsigned abase = sbase + slot * SLOT_BYTES;
        const unsigned bbase = abase + A_STG_BYTES;

        #pragma unroll
        for (int kk = 0; kk < GBK; kk += 16) {
            unsigned a[2][4], b[4][4];
            {
                int kc = (kk >> 3) + akc;
                ldm_x4(a[0], abase + (unsigned)(ar0 * 128 + ((kc ^ (ar0 & 7)) << 4)));
                ldm_x4(a[1], abase + (unsigned)(ar1 * 128 + ((kc ^ (ar1 & 7)) << 4)));
            }
            #pragma unroll
            for (int p = 0; p < 4; ++p) {
                int br = brb + p * 16;
                int kc = (kk >> 3) + bkc;
                ldm_x4(b[p], bbase + (unsigned)(br * 128 + ((kc ^ (br & 7)) << 4)));
            }
            #pragma unroll
            for (int mt = 0; mt < 2; ++mt)
                #pragma unroll
                for (int nt = 0; nt < 8; ++nt)
                    mma_f16(acc[mt][nt], a[mt], &b[nt >> 1][(nt & 1) * 2]);
        }
        // no bottom barrier: iteration c+1's top __syncthreads orders this
        // compute before slot (c+2)%GSTAGES == (c-1)%GSTAGES is overwritten.
    }

    // ---- epilogue ----
    #pragma unroll
    for (int mt = 0; mt < 2; ++mt)
        #pragma unroll
        for (int nt = 0; nt < 8; ++nt) {
            const int row = bm + wm * 32 + mt * 16 + (lane >> 2);
            const int col = bn + wn * 64 + nt * 8 + (lane & 3) * 2;
            const float* c = acc[mt][nt];
            if (OUTH) {
                __half2* out = (__half2*)outp;
                out[(size_t)row * (NOUT / 2) + (col >> 1)] =
                    __halves2half2(__float2half_rn(c[0]), __float2half_rn(c[1]));
                out[(size_t)(row + 8) * (NOUT / 2) + (col >> 1)] =
                    __halves2half2(__float2half_rn(c[2]), __float2half_rn(c[3]));
            } else if (EPI) {
                float* out = (float*)outp;
                float2 d  = *(const float2*)(Dres + col);
                float2 x0 = __half22float2(*(const __half2*)(xres + (size_t)row * NOUT + col));
                float2 x1 = __half22float2(*(const __half2*)(xres + (size_t)(row + 8) * NOUT + col));
                *(float2*)(out + (size_t)row * NOUT + col) =
                    make_float2(c[0] + x0.x * d.x, c[1] + x0.y * d.y);
                *(float2*)(out + (size_t)(row + 8) * NOUT + col) =
                    make_float2(c[2] + x1.x * d.x, c[3] + x1.y * d.y);
            } else {
                float* out = (float*)outp;
                *(float2*)(out + (size_t)row * NOUT + col)       = make_float2(c[0], c[1]);
                *(float2*)(out + (size_t)(row + 8) * NOUT + col) = make_float2(c[2], c[3]);
            }
        }
}

__global__ __launch_bounds__(256, 2) void gemm1_kernel() {
    tc_gemm<HDIM, 2 * NDIM, false, true>(g_xh, g_W2, (void*)g_Buh, nullptr, nullptr);
}

__global__ __launch_bounds__(256, 2) void gemm2_kernel(const float* __restrict__ D,
                                                       float* __restrict__ y) {
    tc_gemm<2 * NDIM, HDIM, true, false>(g_Sh, g_C2, (void*)y, g_xh, D);
}

// ---------------- scanA: segment ends + chunk-end carries -------------------
// block = 1024 threads = 256 cols x 4 segments of 32 steps
__global__ __launch_bounds__(1024) void scanA_kernel() {
    __shared__ float2 e[SEGS * NDIM];
    const int tid = threadIdx.x;
    const int col = tid & 255, seg = tid >> 8;
    const int bc = blockIdx.x;
    const float2 lam = g_Lam[col];
    float2 s = make_float2(0.f, 0.f);
    const __half2* p = g_Buh + (size_t)bc * CHUNK * NDIM
                             + (size_t)seg * SEGLEN * NDIM + col;

    #pragma unroll 1
    for (int j0 = 0; j0 < SEGLEN; j0 += 8) {
        float2 b[8];
        #pragma unroll
        for (int u = 0; u < 8; ++u)
            b[u] = __half22float2(p[(size_t)(j0 + u) * NDIM]);
        #pragma unroll
        for (int u = 0; u < 8; ++u) {
            float sx = fmaf(lam.x, s.x, fmaf(-lam.y, s.y, b[u].x));
            float sy = fmaf(lam.x, s.y, fmaf( lam.y, s.x, b[u].y));
            s = make_float2(sx, sy);
        }
    }
    e[tid] = s;
    g_segE[(size_t)bc * SEGS * NDIM + tid] = s;
    __syncthreads();

    if (tid < NDIM) {
        const float2 l32 = g_Lam32[tid];
        float2 acc = e[tid];
        #pragma unroll
        for (int sg = 1; sg < SEGS; ++sg) {
            float2 es = e[sg * NDIM + tid];
            float ax = fmaf(l32.x, acc.x, fmaf(-l32.y, acc.y, es.x));
            float ay = fmaf(l32.x, acc.y, fmaf( l32.y, acc.x, es.y));
            acc = make_float2(ax, ay);
        }
        g_carryE[(size_t)bc * NDIM + tid] = acc;
    }
}

// ---------------- scanC: carry-aware rescan, emit fp16 states ---------------
__global__ __launch_bounds__(1024) void scanC_kernel() {
    __shared__ float2 cs[SEGS * NDIM];
    const int tid = threadIdx.x;
    const int col = tid & 255, seg = tid >> 8;
    const int bc = blockIdx.x;
    const int b = bc >> 5, c = bc & 31;          // NCHUNK = 32
    const float2 lam = g_Lam[col];
    const __half2* p = g_Buh + (size_t)bc * CHUNK * NDIM
                             + (size_t)seg * SEGLEN * NDIM + col;

    // prologue (threads < 256): chunk carry-in via weighted sum
    if (tid < NDIM) {
        float2 cin = make_float2(0.f, 0.f);
        #pragma unroll 4
        for (int cp = 0; cp < c; ++cp) {
            float2 P = g_LamPowC[(c - 1 - cp) * NDIM + tid];
            float2 E = g_carryE[((size_t)b * NCHUNK + cp) * NDIM + tid];
            cin.x = fmaf(P.x, E.x, fmaf(-P.y, E.y, cin.x));
            cin.y = fmaf(P.x, E.y, fmaf( P.y, E.x, cin.y));
        }
        const float2 l32 = g_Lam32[tid];
        float2 cc = cin;
        cs[tid] = cc;
        #pragma unroll
        for (int sg = 0; sg < SEGS - 1; ++sg) {
            float2 es = g_segE[(size_t)bc * SEGS * NDIM + sg * NDIM + tid];
            float cx = fmaf(l32.x, cc.x, fmaf(-l32.y, cc.y, es.x));
            float cy = fmaf(l32.x, cc.y, fmaf( l32.y, cc.x, es.y));
            cc = make_float2(cx, cy);
            cs[(sg + 1) * NDIM + tid] = cc;
        }
    }
    __syncthreads();

    // rescan from carry-in, write fp16 states
    {
        float2 s = cs[tid];
        __half2* o = (__half2*)g_Sh + (size_t)bc * CHUNK * NDIM
                                    + (size_t)seg * SEGLEN * NDIM + col;
        #pragma unroll 1
        for (int j0 = 0; j0 < SEGLEN; j0 += 8) {
            float2 b8[8];
            #pragma unroll
            for (int u = 0; u < 8; ++u)
                b8[u] = __half22float2(p[(size_t)(j0 + u) * NDIM]);
            #pragma unroll
            for (int u = 0; u < 8; ++u) {
                float sx = fmaf(lam.x, s.x, fmaf(-lam.y, s.y, b8[u].x));
                float sy = fmaf(lam.x, s.y, fmaf( lam.y, s.x, b8[u].y));
                s = make_float2(sx, sy);
                o[(size_t)(j0 + u) * NDIM] =
                    __halves2half2(__float2half_rn(sx), __float2half_rn(sy));
            }
        }
    }
}

// ---------------- launch -----------------------------------------------------
extern "C" void kernel_launch(void* const* d_in, const int* in_sizes, int n_in,
                              void* d_out, int out_size) {
    const float* x         = (const float*)d_in[0];
    const float* B_re      = (const float*)d_in[1];
    const float* B_im      = (const float*)d_in[2];
    const float* C_re      = (const float*)d_in[3];
    const float* C_im      = (const float*)d_in[4];
    const float* nu_log    = (const float*)d_in[5];
    const float* theta_log = (const float*)d_in[6];
    const float* D         = (const float*)d_in[7];
    float* y = (float*)d_out;

    cudaFuncSetAttribute(gemm1_kernel,
                         cudaFuncAttributeMaxDynamicSharedMemorySize, G_SMEM_BYTES);
    cudaFuncSetAttribute(gemm2_kernel,
                         cudaFuncAttributeMaxDynamicSharedMemorySize, G_SMEM_BYTES);

    prep_kernel<<<PX_BLOCKS + NDIM + HDIM + 1, 256>>>(x, nu_log, theta_log,
                                                      B_re, B_im, C_re, C_im);
    gemm1_kernel<<<dim3((2 * NDIM) / 128, BL / 128), 256, G_SMEM_BYTES>>>();
    scanA_kernel<<<B_SZ * NCHUNK, 1024>>>();
    scanC_kernel<<<B_SZ * NCHUNK, 1024>>>();
    gemm2_kernel<<<dim3(HDIM / 128, BL / 128), 256, G_SMEM_BYTES>>>(D, y);
}